// round 16
// baseline (speedup 1.0000x reference)
#include <cuda_runtime.h>
#include <cuda_fp16.h>
#include <math.h>
#include <stdint.h>

#define BATCH  65536
#define DIM    512
#define NPROTO 1024

// ---------------- device scratch ----------------
__device__ __half g_xh[(size_t)BATCH * DIM];
__device__ __half g_Wh[(size_t)DIM * DIM];
__device__ __half g_WTh[(size_t)DIM * DIM],    g_WTl[(size_t)DIM * DIM];
__device__ __half g_PTh[(size_t)DIM * NPROTO];
__device__ __half g_Qh[(size_t)NPROTO * DIM],  g_Ql[(size_t)NPROTO * DIM];
__device__ __half g_wh[(size_t)BATCH * NPROTO];
__device__ float g_zsq[BATCH];
__device__ float g_psq2[NPROTO];   // psq - 2*P.b

// ======================= helpers =======================
__device__ __forceinline__ uint32_t smem_u32(const void* p) {
    uint32_t a;
    asm("{ .reg .u64 t; cvta.to.shared.u64 t, %1; cvt.u32.u64 %0, t; }" : "=r"(a) : "l"(p));
    return a;
}

#define LDSM4(r, addr) \
    asm volatile("ldmatrix.sync.aligned.m8n8.x4.shared.b16 {%0,%1,%2,%3}, [%4];" \
        : "=r"((r)[0]), "=r"((r)[1]), "=r"((r)[2]), "=r"((r)[3]) : "r"(addr))

#define MMA16816(d, a, b0, b1) \
    asm volatile("mma.sync.aligned.m16n8k16.row.col.f32.f16.f16.f32 " \
        "{%0,%1,%2,%3}, {%4,%5,%6,%7}, {%8,%9}, {%0,%1,%2,%3};" \
        : "+f"((d)[0]), "+f"((d)[1]), "+f"((d)[2]), "+f"((d)[3]) \
        : "r"((a)[0]), "r"((a)[1]), "r"((a)[2]), "r"((a)[3]), "r"(b0), "r"(b1))

#define CP16(dst, src) \
    asm volatile("cp.async.cg.shared.global [%0], [%1], 16;" :: "r"(dst), "l"(src))
#define CP_COMMIT() asm volatile("cp.async.commit_group;" ::: "memory")
#define CP_WAIT1()  asm volatile("cp.async.wait_group 1;" ::: "memory")
#define CP_WAIT0()  asm volatile("cp.async.wait_group 0;" ::: "memory")

__device__ __forceinline__ void split_pair(float x, float y, uint32_t& hi, uint32_t& lo) {
    __half hx = __float2half_rn(x), hy = __float2half_rn(y);
    __half2 h2 = __halves2half2(hx, hy);
    hi = *(uint32_t*)&h2;
    __half2 l2 = __floats2half2_rn(x - __half2float(hx), y - __half2float(hy));
    lo = *(uint32_t*)&l2;
}
__device__ __forceinline__ void cvt8(const float4& a, const float4& b,
                                     uint4& hi, uint4& lo) {
    split_pair(a.x, a.y, hi.x, lo.x);
    split_pair(a.z, a.w, hi.y, lo.y);
    split_pair(b.x, b.y, hi.z, lo.z);
    split_pair(b.z, b.w, hi.w, lo.w);
}

// FFMA-pipe exp (args <= 0 here)
__device__ __forceinline__ float fexp(float x) {
    float y = x * 1.4426950408889634f;
    float t = y + 12582912.0f;
    float n = t - 12582912.0f;
    float f = y - n;
    float p = 1.3333558146e-3f;
    p = fmaf(p, f, 9.6181291076e-3f);
    p = fmaf(p, f, 5.5504108664e-2f);
    p = fmaf(p, f, 2.4022650696e-1f);
    p = fmaf(p, f, 6.9314718056e-1f);
    p = fmaf(p, f, 1.0f);
    return __int_as_float(__float_as_int(p) + (((int)n) << 23));
}

// ======================= 3-pass kernel smem (BK=16, 48B rows) =================
#define MATB   6144u
#define BUFB   (4u * MATB)
#define SMEM_TOTAL (2 * BUFB)   // 49152

// ======================= 1-pass kernel smem (BK=64, 144B rows, cp.async) ======
#define MAT64  18432u            // 128 rows * 144 B
#define BUF64  (2u * MAT64)      // A + B
#define SMEM64 (2 * BUF64)       // 73728

// ======================= 3-pass HMMA GEMM NT (Q = P@W only) ===================
__global__ __launch_bounds__(256, 2) void hmma_gemm3p(
    const float* __restrict__ Afg0,
    const __half* __restrict__ Bh, const __half* __restrict__ Bl,
    __half* __restrict__ oh, __half* __restrict__ ol,
    int K, int ldc) {
    extern __shared__ __align__(128) char smem[];
    const uint32_t sb = smem_u32(smem);
    const int tid = threadIdx.x;
    const int wid = tid >> 5, lane = tid & 31;
    const size_t bm = (size_t)blockIdx.y * 128;
    const size_t bn = (size_t)blockIdx.x * 128;
    const int warp_m = (wid >> 1) * 32;
    const int warp_n = (wid & 1) * 64;

    float acc[2][8][4];
#pragma unroll
    for (int i = 0; i < 2; i++)
#pragma unroll
        for (int j = 0; j < 8; j++)
#pragma unroll
            for (int k = 0; k < 4; k++) acc[i][j][k] = 0.0f;

    const float*  Afg = Afg0 + bm * K;
    const __half* Bhg = Bh + bn * K;
    const __half* Blg = Bl + bn * K;
    const int NC = K >> 4;

    const int f_r = tid >> 1;
    const int f_s = (tid & 1) << 3;
    const uint32_t soff = (uint32_t)(f_r * 48 + (tid & 1) * 16);

    {
        float4 a0 = *(const float4*)(Afg + (size_t)f_r * K + f_s);
        float4 a1 = *(const float4*)(Afg + (size_t)f_r * K + f_s + 4);
        uint4 hi, lo;
        cvt8(a0, a1, hi, lo);
        *(uint4*)(smem + soff) = hi;
        *(uint4*)(smem + MATB + soff) = lo;
        *(uint4*)(smem + 2 * MATB + soff) = *(const uint4*)(Bhg + (size_t)f_r * K + f_s);
        *(uint4*)(smem + 3 * MATB + soff) = *(const uint4*)(Blg + (size_t)f_r * K + f_s);
    }
    __syncthreads();

    const int a_row = lane & 15;
    const int a_kb = ((lane >> 4) << 3) * 2;
    const int b_n = ((lane >> 4) << 3) + (lane & 7);
    const int b_kb = (lane & 8) * 2;

    uint4 pbh, pbl;
    float4 pfa0, pfa1;
    for (int c = 0; c < NC; ++c) {
        const int buf = c & 1;
        const uint32_t base = sb + buf * BUFB;

        if (c + 1 < NC) {
            const int k0 = (c + 1) << 4;
            pfa0 = *(const float4*)(Afg + (size_t)f_r * K + k0 + f_s);
            pfa1 = *(const float4*)(Afg + (size_t)f_r * K + k0 + f_s + 4);
            pbh = *(const uint4*)(Bhg + (size_t)f_r * K + k0 + f_s);
            pbl = *(const uint4*)(Blg + (size_t)f_r * K + k0 + f_s);
        }

        uint32_t ah[2][4], al[2][4];
#pragma unroll
        for (int i = 0; i < 2; i++) {
            uint32_t ra = base + (uint32_t)((warp_m + i * 16 + a_row) * 48) + a_kb;
            LDSM4(ah[i], ra);
            LDSM4(al[i], ra + MATB);
        }
#pragma unroll
        for (int jp = 0; jp < 4; jp++) {
            uint32_t rb = base + 2 * MATB +
                          (uint32_t)((warp_n + jp * 16 + b_n) * 48) + b_kb;
            uint32_t bh[4], bl[4];
            LDSM4(bh, rb);
            LDSM4(bl, rb + MATB);
#pragma unroll
            for (int i = 0; i < 2; i++) {
                MMA16816(acc[i][jp * 2 + 0], ah[i], bh[0], bh[1]);
                MMA16816(acc[i][jp * 2 + 0], ah[i], bl[0], bl[1]);
                MMA16816(acc[i][jp * 2 + 0], al[i], bh[0], bh[1]);
                MMA16816(acc[i][jp * 2 + 1], ah[i], bh[2], bh[3]);
                MMA16816(acc[i][jp * 2 + 1], ah[i], bl[2], bl[3]);
                MMA16816(acc[i][jp * 2 + 1], al[i], bh[2], bh[3]);
            }
        }

        if (c + 1 < NC) {
            const uint32_t nb = (buf ^ 1) * BUFB;
            uint4 hi, lo;
            cvt8(pfa0, pfa1, hi, lo);
            *(uint4*)(smem + nb + soff) = hi;
            *(uint4*)(smem + nb + MATB + soff) = lo;
            *(uint4*)(smem + nb + 2 * MATB + soff) = pbh;
            *(uint4*)(smem + nb + 3 * MATB + soff) = pbl;
        }
        __syncthreads();
    }

    const int rbase = warp_m + (lane >> 2);
    const int cbase = warp_n + (lane & 3) * 2;
#pragma unroll
    for (int i = 0; i < 2; i++) {
#pragma unroll
        for (int h = 0; h < 2; h++) {
            const size_t row = bm + rbase + i * 16 + h * 8;
#pragma unroll
            for (int j = 0; j < 8; j++) {
                const int cg = cbase + j * 8;
                uint32_t hi, lo;
                split_pair(acc[i][j][h * 2 + 0], acc[i][j][h * 2 + 1], hi, lo);
                *(uint32_t*)(oh + row * (size_t)ldc + bn + cg) = hi;
                *(uint32_t*)(ol + row * (size_t)ldc + bn + cg) = lo;
            }
        }
    }
}

// ======================= BK=64 cp.async fill helper pattern ====================
// Each thread: row f_r = tid>>1, half f_h = tid&1 (64B = 4x16B segments).
// smem so = f_r*144 + f_h*64 ; gmem halves offset f_h*32 + k*8.

// fused logits+zsq: grid (12, BATCH/128); x<8: Sraw = xh.Qh^T ; x>=8: zsq
__global__ __launch_bounds__(256, 2) void fused_logits_zsq_ca64(
    const __half* __restrict__ xh,
    const __half* __restrict__ Qh,
    const __half* __restrict__ Wh, const float* __restrict__ bias,
    float* __restrict__ Sraw, float* __restrict__ zsq) {
    extern __shared__ __align__(128) char smem[];
    const uint32_t sb = smem_u32(smem);
    const int tid = threadIdx.x;
    const int wid = tid >> 5, lane = tid & 31;
    const bool is_w = blockIdx.x >= 8;
    const size_t bm = (size_t)blockIdx.y * 128;
    const size_t bn = is_w ? (size_t)(blockIdx.x - 8) * 128 : (size_t)blockIdx.x * 128;
    const int warp_m = (wid >> 1) * 32;
    const int warp_n = (wid & 1) * 64;
    const int K = DIM, NC = DIM >> 6;   // 8 chunks of 64

    float acc[2][8][4];
#pragma unroll
    for (int i = 0; i < 2; i++)
#pragma unroll
        for (int j = 0; j < 8; j++)
#pragma unroll
            for (int k = 0; k < 4; k++) acc[i][j][k] = 0.0f;

    const __half* Ahg = xh + bm * K;
    const __half* Bhg = (is_w ? Wh : Qh) + bn * K;

    const int f_r = tid >> 1;
    const int f_h = tid & 1;
    const uint32_t so = (uint32_t)(f_r * 144 + f_h * 64);
    const __half* ag = Ahg + (size_t)f_r * K + f_h * 32;
    const __half* bg = Bhg + (size_t)f_r * K + f_h * 32;

    // prologue: chunk 0 -> buf 0
    {
#pragma unroll
        for (int k = 0; k < 4; k++) {
            CP16(sb + so + k * 16, ag + k * 8);
            CP16(sb + MAT64 + so + k * 16, bg + k * 8);
        }
        CP_COMMIT();
    }

    const int a_row = lane & 15;
    const int a_kb = ((lane >> 4) << 3) * 2;
    const int b_n = ((lane >> 4) << 3) + (lane & 7);
    const int b_kb = (lane & 8) * 2;

    for (int c = 0; c < NC; ++c) {
        const int buf = c & 1;
        const uint32_t base = sb + buf * BUF64;

        if (c + 1 < NC) {
            const uint32_t nb = sb + (buf ^ 1) * BUF64;
            const int k0 = (c + 1) << 6;
#pragma unroll
            for (int k = 0; k < 4; k++) {
                CP16(nb + so + k * 16, ag + k0 + k * 8);
                CP16(nb + MAT64 + so + k * 16, bg + k0 + k * 8);
            }
            CP_COMMIT();
            CP_WAIT1();
        } else {
            CP_WAIT0();
        }
        __syncthreads();

#pragma unroll
        for (int kk = 0; kk < 4; kk++) {
            const int kb = kk * 32;
            uint32_t ah[2][4];
#pragma unroll
            for (int i = 0; i < 2; i++) {
                uint32_t ra = base + (uint32_t)((warp_m + i * 16 + a_row) * 144) + kb + a_kb;
                LDSM4(ah[i], ra);
            }
#pragma unroll
            for (int jp = 0; jp < 4; jp++) {
                uint32_t rb = base + MAT64 +
                              (uint32_t)((warp_n + jp * 16 + b_n) * 144) + kb + b_kb;
                uint32_t bh[4];
                LDSM4(bh, rb);
#pragma unroll
                for (int i = 0; i < 2; i++) {
                    MMA16816(acc[i][jp * 2 + 0], ah[i], bh[0], bh[1]);
                    MMA16816(acc[i][jp * 2 + 1], ah[i], bh[2], bh[3]);
                }
            }
        }
        __syncthreads();
    }

    const int rbase = warp_m + (lane >> 2);
    const int cbase = warp_n + (lane & 3) * 2;
#pragma unroll
    for (int i = 0; i < 2; i++) {
#pragma unroll
        for (int h = 0; h < 2; h++) {
            const size_t row = bm + rbase + i * 16 + h * 8;
            if (is_w) {
                float s = 0.0f;
#pragma unroll
                for (int j = 0; j < 8; j++) {
                    const int cg = cbase + j * 8;
                    float v0 = acc[i][j][h * 2 + 0] + bias[bn + cg];
                    float v1 = acc[i][j][h * 2 + 1] + bias[bn + cg + 1];
                    s += v0 * v0 + v1 * v1;
                }
                s += __shfl_xor_sync(0xffffffffu, s, 1);
                s += __shfl_xor_sync(0xffffffffu, s, 2);
                if ((lane & 3) == 0) atomicAdd(zsq + row, s);
            } else {
                float* crow = Sraw + row * (size_t)NPROTO + bn;
#pragma unroll
                for (int j = 0; j < 8; j++) {
                    const int cg = cbase + j * 8;
                    *(float2*)(crow + cg) =
                        make_float2(acc[i][j][h * 2 + 0], acc[i][j][h * 2 + 1]);
                }
            }
        }
    }
}

// blended = A(fp16) @ B(fp16)^T, 1-pass, BK=64 cp.async, fp32 out
__global__ __launch_bounds__(256, 2) void hmma_gemm1p_ca64(
    const __half* __restrict__ Ah, const __half* __restrict__ Bh,
    float* __restrict__ C, int K, int ldc) {
    extern __shared__ __align__(128) char smem[];
    const uint32_t sb = smem_u32(smem);
    const int tid = threadIdx.x;
    const int wid = tid >> 5, lane = tid & 31;
    const size_t bm = (size_t)blockIdx.y * 128;
    const size_t bn = (size_t)blockIdx.x * 128;
    const int warp_m = (wid >> 1) * 32;
    const int warp_n = (wid & 1) * 64;
    const int NC = K >> 6;

    float acc[2][8][4];
#pragma unroll
    for (int i = 0; i < 2; i++)
#pragma unroll
        for (int j = 0; j < 8; j++)
#pragma unroll
            for (int k = 0; k < 4; k++) acc[i][j][k] = 0.0f;

    const __half* Ahg = Ah + bm * K;
    const __half* Bhg = Bh + bn * K;

    const int f_r = tid >> 1;
    const int f_h = tid & 1;
    const uint32_t so = (uint32_t)(f_r * 144 + f_h * 64);
    const __half* ag = Ahg + (size_t)f_r * K + f_h * 32;
    const __half* bg = Bhg + (size_t)f_r * K + f_h * 32;

    {
#pragma unroll
        for (int k = 0; k < 4; k++) {
            CP16(sb + so + k * 16, ag + k * 8);
            CP16(sb + MAT64 + so + k * 16, bg + k * 8);
        }
        CP_COMMIT();
    }

    const int a_row = lane & 15;
    const int a_kb = ((lane >> 4) << 3) * 2;
    const int b_n = ((lane >> 4) << 3) + (lane & 7);
    const int b_kb = (lane & 8) * 2;

    for (int c = 0; c < NC; ++c) {
        const int buf = c & 1;
        const uint32_t base = sb + buf * BUF64;

        if (c + 1 < NC) {
            const uint32_t nb = sb + (buf ^ 1) * BUF64;
            const int k0 = (c + 1) << 6;
#pragma unroll
            for (int k = 0; k < 4; k++) {
                CP16(nb + so + k * 16, ag + k0 + k * 8);
                CP16(nb + MAT64 + so + k * 16, bg + k0 + k * 8);
            }
            CP_COMMIT();
            CP_WAIT1();
        } else {
            CP_WAIT0();
        }
        __syncthreads();

#pragma unroll
        for (int kk = 0; kk < 4; kk++) {
            const int kb = kk * 32;
            uint32_t ah[2][4];
#pragma unroll
            for (int i = 0; i < 2; i++) {
                uint32_t ra = base + (uint32_t)((warp_m + i * 16 + a_row) * 144) + kb + a_kb;
                LDSM4(ah[i], ra);
            }
#pragma unroll
            for (int jp = 0; jp < 4; jp++) {
                uint32_t rb = base + MAT64 +
                              (uint32_t)((warp_n + jp * 16 + b_n) * 144) + kb + b_kb;
                uint32_t bh[4];
                LDSM4(bh, rb);
#pragma unroll
                for (int i = 0; i < 2; i++) {
                    MMA16816(acc[i][jp * 2 + 0], ah[i], bh[0], bh[1]);
                    MMA16816(acc[i][jp * 2 + 1], ah[i], bh[2], bh[3]);
                }
            }
        }
        __syncthreads();
    }

    const int rbase = warp_m + (lane >> 2);
    const int cbase = warp_n + (lane & 3) * 2;
#pragma unroll
    for (int i = 0; i < 2; i++) {
#pragma unroll
        for (int h = 0; h < 2; h++) {
            const size_t row = bm + rbase + i * 16 + h * 8;
            float* crow = C + row * (size_t)ldc + bn;
#pragma unroll
            for (int j = 0; j < 8; j++) {
                const int cg = cbase + j * 8;
                *(float2*)(crow + cg) =
                    make_float2(acc[i][j][h * 2 + 0], acc[i][j][h * 2 + 1]);
            }
        }
    }
}

// ======================= small kernels =======================
__device__ __forceinline__ float wsum(float v) {
#pragma unroll
    for (int o = 16; o; o >>= 1) v += __shfl_xor_sync(0xffffffffu, v, o);
    return v;
}
__device__ __forceinline__ float wmax(float v) {
#pragma unroll
    for (int o = 16; o; o >>= 1) v = fmaxf(v, __shfl_xor_sync(0xffffffffu, v, o));
    return v;
}

// psq2[row] = sum(P[row]^2) - 2 * dot(P[row], b)
__global__ __launch_bounds__(128) void row_psq2(const float* __restrict__ P,
                                                const float* __restrict__ b,
                                                float* __restrict__ out) {
    size_t row = blockIdx.x;
    const float4* p = (const float4*)(P + row * 512);
    float4 v = p[threadIdx.x];
    float4 bb = ((const float4*)b)[threadIdx.x];
    float s = v.x * v.x + v.y * v.y + v.z * v.z + v.w * v.w
            - 2.0f * (v.x * bb.x + v.y * bb.y + v.z * bb.z + v.w * bb.w);
    s = wsum(s);
    __shared__ float red[4];
    if ((threadIdx.x & 31) == 0) red[threadIdx.x >> 5] = s;
    __syncthreads();
    if (threadIdx.x == 0) out[row] = red[0] + red[1] + red[2] + red[3];
}

// dist + softmax over rows of 1024; reads raw dot, writes fp32 weights + fp16 hi
__global__ __launch_bounds__(256) void softmax_dist_1024(
    float* __restrict__ Wt, const float* __restrict__ zsq,
    const float* __restrict__ psq2, const float* __restrict__ temp_raw,
    __half* __restrict__ wh) {
    size_t row = blockIdx.x;
    float4* p = (float4*)(Wt + row * 1024);
    float4 s4 = p[threadIdx.x];
    float4 pq = ((const float4*)psq2)[threadIdx.x];
    float zr = zsq[row];
    float t = temp_raw[0];
    float temp = 1.0f / (1.0f + expf(-t)) * 0.999f + 0.001f;
    float invt = 1.0f / temp;

    float4 v;
    v.x = -sqrtf(fmaxf(zr + pq.x - 2.0f * s4.x, 1e-12f)) * invt;
    v.y = -sqrtf(fmaxf(zr + pq.y - 2.0f * s4.y, 1e-12f)) * invt;
    v.z = -sqrtf(fmaxf(zr + pq.z - 2.0f * s4.z, 1e-12f)) * invt;
    v.w = -sqrtf(fmaxf(zr + pq.w - 2.0f * s4.w, 1e-12f)) * invt;

    __shared__ float red[8];
    float m = fmaxf(fmaxf(v.x, v.y), fmaxf(v.z, v.w));
    m = wmax(m);
    if ((threadIdx.x & 31) == 0) red[threadIdx.x >> 5] = m;
    __syncthreads();
    if (threadIdx.x < 32) {
        float q = (threadIdx.x < 8) ? red[threadIdx.x] : -INFINITY;
        q = wmax(q);
        if (threadIdx.x == 0) red[0] = q;
    }
    __syncthreads();
    m = red[0];
    __syncthreads();

    v.x = fexp(v.x - m); v.y = fexp(v.y - m);
    v.z = fexp(v.z - m); v.w = fexp(v.w - m);
    float s = v.x + v.y + v.z + v.w;
    s = wsum(s);
    __shared__ float red2[8];
    if ((threadIdx.x & 31) == 0) red2[threadIdx.x >> 5] = s;
    __syncthreads();
    if (threadIdx.x < 32) {
        float q = (threadIdx.x < 8) ? red2[threadIdx.x] : 0.0f;
        q = wsum(q);
        if (threadIdx.x == 0) red2[0] = q;
    }
    __syncthreads();
    float inv = 1.0f / red2[0];
    v.x *= inv; v.y *= inv; v.z *= inv; v.w *= inv;
    p[threadIdx.x] = v;

    __half2 h0 = __floats2half2_rn(v.x, v.y);
    __half2 h1 = __floats2half2_rn(v.z, v.w);
    *(uint2*)(wh + row * 1024 + threadIdx.x * 4) =
        make_uint2(*(uint32_t*)&h0, *(uint32_t*)&h1);
}

// convert fp32 array to fp16 (hi only)
__global__ __launch_bounds__(256) void split_hi(const float4* __restrict__ src,
                                                uint2* __restrict__ hi, int n4) {
    int i = blockIdx.x * 256 + threadIdx.x;
    if (i >= n4) return;
    float4 v = src[i];
    __half2 h0 = __floats2half2_rn(v.x, v.y);
    __half2 h1 = __floats2half2_rn(v.z, v.w);
    hi[i] = make_uint2(*(uint32_t*)&h0, *(uint32_t*)&h1);
}

// transpose + split: src [rows, cols] fp32 -> dst [cols, rows] fp16 hi (+ optional lo)
__global__ __launch_bounds__(256) void transpose_split(const float* __restrict__ src,
                                                       __half* __restrict__ dh,
                                                       __half* __restrict__ dl,
                                                       int rows, int cols) {
    __shared__ float t[32][33];
    int bx = blockIdx.x * 32;
    int by = blockIdx.y * 32;
    int tx = threadIdx.x & 31, ty = (threadIdx.x >> 5) * 4;
#pragma unroll
    for (int i = 0; i < 4; i++)
        t[ty + i][tx] = src[(size_t)(by + ty + i) * cols + bx + tx];
    __syncthreads();
#pragma unroll
    for (int i = 0; i < 4; i++) {
        float v = t[tx][ty + i];
        __half hv = __float2half_rn(v);
        size_t off = (size_t)(bx + ty + i) * rows + by + tx;
        dh[off] = hv;
        if (dl) dl[off] = __float2half_rn(v - __half2float(hv));
    }
}

extern "C" void kernel_launch(void* const* d_in, const int* in_sizes, int n_in,
                              void* d_out, int out_size) {
    const float* x  = (const float*)d_in[0];
    const float* W  = (const float*)d_in[1];
    const float* b  = (const float*)d_in[2];
    const float* P  = (const float*)d_in[3];
    const float* tr = (const float*)d_in[4];

    float* blended = (float*)d_out;
    float* weights = (float*)d_out + (size_t)BATCH * DIM;

    __half *xh, *Wh, *WTh, *WTl, *PTh, *Qh, *Ql, *wh;
    float *zsq, *psq2;
    cudaGetSymbolAddress((void**)&xh, g_xh);
    cudaGetSymbolAddress((void**)&Wh, g_Wh);
    cudaGetSymbolAddress((void**)&WTh, g_WTh); cudaGetSymbolAddress((void**)&WTl, g_WTl);
    cudaGetSymbolAddress((void**)&PTh, g_PTh);
    cudaGetSymbolAddress((void**)&Qh, g_Qh);   cudaGetSymbolAddress((void**)&Ql, g_Ql);
    cudaGetSymbolAddress((void**)&wh, g_wh);
    cudaGetSymbolAddress((void**)&zsq, g_zsq); cudaGetSymbolAddress((void**)&psq2, g_psq2);

    cudaFuncSetAttribute((const void*)hmma_gemm3p, cudaFuncAttributeMaxDynamicSharedMemorySize, SMEM_TOTAL);
    cudaFuncSetAttribute((const void*)fused_logits_zsq_ca64, cudaFuncAttributeMaxDynamicSharedMemorySize, SMEM64);
    cudaFuncSetAttribute((const void*)hmma_gemm1p_ca64, cudaFuncAttributeMaxDynamicSharedMemorySize, SMEM64);

    cudaMemsetAsync(zsq, 0, BATCH * sizeof(float));

    // psq2 = |p|^2 - 2 p.b
    row_psq2<<<NPROTO, 128>>>(P, b, psq2);

    // operand prep
    split_hi<<<(BATCH * DIM / 4 + 255) / 256, 256>>>((const float4*)x, (uint2*)xh, BATCH * DIM / 4);
    split_hi<<<(DIM * DIM / 4 + 255) / 256, 256>>>((const float4*)W, (uint2*)Wh, DIM * DIM / 4);
    transpose_split<<<dim3(16, 16), 256>>>(W, WTh, WTl, DIM, DIM);
    transpose_split<<<dim3(16, 32), 256>>>(P, PTh, nullptr, NPROTO, DIM);

    // Q = P @ W (3-pass, fp32-accurate), write fp16 hi/lo
    hmma_gemm3p<<<dim3(DIM / 128, NPROTO / 128), 256, SMEM_TOTAL>>>(
        P, WTh, WTl, Qh, Ql, DIM, DIM);

    // fused: Sraw = xh.Qh^T + zsq (both 1-pass, BK=64, cp.async)
    fused_logits_zsq_ca64<<<dim3(12, BATCH / 128), 256, SMEM64>>>(
        xh, Qh, Wh, b, weights, zsq);

    // dist + softmax; writes fp32 weights + fp16 wh
    softmax_dist_1024<<<BATCH, 256>>>(weights, zsq, psq2, tr, wh);

    // blended = weights @ P (1-pass, BK=64, cp.async)
    hmma_gemm1p_ca64<<<dim3(DIM / 128, BATCH / 128), 256, SMEM64>>>(
        wh, PTh, blended, NPROTO, DIM);
}

// round 17
// speedup vs baseline: 1.1333x; 1.1333x over previous
#include <cuda_runtime.h>
#include <cuda_fp16.h>
#include <math.h>
#include <stdint.h>

#define BATCH  65536
#define DIM    512
#define NPROTO 1024

// ---------------- device scratch ----------------
__device__ __half g_xh[(size_t)BATCH * DIM];
__device__ __half g_Wh[(size_t)DIM * DIM];
__device__ __half g_WTh[(size_t)DIM * DIM],    g_WTl[(size_t)DIM * DIM];
__device__ __half g_PTh[(size_t)DIM * NPROTO];
__device__ __half g_Qh[(size_t)NPROTO * DIM],  g_Ql[(size_t)NPROTO * DIM];
__device__ __half g_sw[(size_t)BATCH * NPROTO];  // Sraw (fp16) then weights (fp16)
__device__ float g_zsq[BATCH];
__device__ float g_psq2[NPROTO];   // psq - 2*P.b

// ======================= helpers =======================
__device__ __forceinline__ uint32_t smem_u32(const void* p) {
    uint32_t a;
    asm("{ .reg .u64 t; cvta.to.shared.u64 t, %1; cvt.u32.u64 %0, t; }" : "=r"(a) : "l"(p));
    return a;
}

#define LDSM4(r, addr) \
    asm volatile("ldmatrix.sync.aligned.m8n8.x4.shared.b16 {%0,%1,%2,%3}, [%4];" \
        : "=r"((r)[0]), "=r"((r)[1]), "=r"((r)[2]), "=r"((r)[3]) : "r"(addr))

#define MMA16816(d, a, b0, b1) \
    asm volatile("mma.sync.aligned.m16n8k16.row.col.f32.f16.f16.f32 " \
        "{%0,%1,%2,%3}, {%4,%5,%6,%7}, {%8,%9}, {%0,%1,%2,%3};" \
        : "+f"((d)[0]), "+f"((d)[1]), "+f"((d)[2]), "+f"((d)[3]) \
        : "r"((a)[0]), "r"((a)[1]), "r"((a)[2]), "r"((a)[3]), "r"(b0), "r"(b1))

__device__ __forceinline__ void split_pair(float x, float y, uint32_t& hi, uint32_t& lo) {
    __half hx = __float2half_rn(x), hy = __float2half_rn(y);
    __half2 h2 = __halves2half2(hx, hy);
    hi = *(uint32_t*)&h2;
    __half2 l2 = __floats2half2_rn(x - __half2float(hx), y - __half2float(hy));
    lo = *(uint32_t*)&l2;
}
__device__ __forceinline__ void cvt8(const float4& a, const float4& b,
                                     uint4& hi, uint4& lo) {
    split_pair(a.x, a.y, hi.x, lo.x);
    split_pair(a.z, a.w, hi.y, lo.y);
    split_pair(b.x, b.y, hi.z, lo.z);
    split_pair(b.z, b.w, hi.w, lo.w);
}

// FFMA-pipe exp (args <= 0 here)
__device__ __forceinline__ float fexp(float x) {
    float y = x * 1.4426950408889634f;
    float t = y + 12582912.0f;
    float n = t - 12582912.0f;
    float f = y - n;
    float p = 1.3333558146e-3f;
    p = fmaf(p, f, 9.6181291076e-3f);
    p = fmaf(p, f, 5.5504108664e-2f);
    p = fmaf(p, f, 2.4022650696e-1f);
    p = fmaf(p, f, 6.9314718056e-1f);
    p = fmaf(p, f, 1.0f);
    return __int_as_float(__float_as_int(p) + (((int)n) << 23));
}

// ======================= 3-pass kernel smem (BK=16, 48B rows) =================
#define MATB   6144u
#define BUFB   (4u * MATB)
#define SMEM_TOTAL (2 * BUFB)   // 49152

// ======================= 1-pass kernel smem (BK=32, 80B rows) =================
#define MAT32  10240u            // 128 rows * 80 B
#define BUF32  (2u * MAT32)      // A + B
#define SMEM32 (2 * BUF32)       // 40960

// ======================= 3-pass HMMA GEMM NT (Q = P@W only) ===================
__global__ __launch_bounds__(256, 2) void hmma_gemm3p(
    const float* __restrict__ Afg0,
    const __half* __restrict__ Bh, const __half* __restrict__ Bl,
    __half* __restrict__ oh, __half* __restrict__ ol,
    int K, int ldc) {
    extern __shared__ __align__(128) char smem[];
    const uint32_t sb = smem_u32(smem);
    const int tid = threadIdx.x;
    const int wid = tid >> 5, lane = tid & 31;
    const size_t bm = (size_t)blockIdx.y * 128;
    const size_t bn = (size_t)blockIdx.x * 128;
    const int warp_m = (wid >> 1) * 32;
    const int warp_n = (wid & 1) * 64;

    float acc[2][8][4];
#pragma unroll
    for (int i = 0; i < 2; i++)
#pragma unroll
        for (int j = 0; j < 8; j++)
#pragma unroll
            for (int k = 0; k < 4; k++) acc[i][j][k] = 0.0f;

    const float*  Afg = Afg0 + bm * K;
    const __half* Bhg = Bh + bn * K;
    const __half* Blg = Bl + bn * K;
    const int NC = K >> 4;

    const int f_r = tid >> 1;
    const int f_s = (tid & 1) << 3;
    const uint32_t soff = (uint32_t)(f_r * 48 + (tid & 1) * 16);

    {
        float4 a0 = *(const float4*)(Afg + (size_t)f_r * K + f_s);
        float4 a1 = *(const float4*)(Afg + (size_t)f_r * K + f_s + 4);
        uint4 hi, lo;
        cvt8(a0, a1, hi, lo);
        *(uint4*)(smem + soff) = hi;
        *(uint4*)(smem + MATB + soff) = lo;
        *(uint4*)(smem + 2 * MATB + soff) = *(const uint4*)(Bhg + (size_t)f_r * K + f_s);
        *(uint4*)(smem + 3 * MATB + soff) = *(const uint4*)(Blg + (size_t)f_r * K + f_s);
    }
    __syncthreads();

    const int a_row = lane & 15;
    const int a_kb = ((lane >> 4) << 3) * 2;
    const int b_n = ((lane >> 4) << 3) + (lane & 7);
    const int b_kb = (lane & 8) * 2;

    uint4 pbh, pbl;
    float4 pfa0, pfa1;
    for (int c = 0; c < NC; ++c) {
        const int buf = c & 1;
        const uint32_t base = sb + buf * BUFB;

        if (c + 1 < NC) {
            const int k0 = (c + 1) << 4;
            pfa0 = *(const float4*)(Afg + (size_t)f_r * K + k0 + f_s);
            pfa1 = *(const float4*)(Afg + (size_t)f_r * K + k0 + f_s + 4);
            pbh = *(const uint4*)(Bhg + (size_t)f_r * K + k0 + f_s);
            pbl = *(const uint4*)(Blg + (size_t)f_r * K + k0 + f_s);
        }

        uint32_t ah[2][4], al[2][4];
#pragma unroll
        for (int i = 0; i < 2; i++) {
            uint32_t ra = base + (uint32_t)((warp_m + i * 16 + a_row) * 48) + a_kb;
            LDSM4(ah[i], ra);
            LDSM4(al[i], ra + MATB);
        }
#pragma unroll
        for (int jp = 0; jp < 4; jp++) {
            uint32_t rb = base + 2 * MATB +
                          (uint32_t)((warp_n + jp * 16 + b_n) * 48) + b_kb;
            uint32_t bh[4], bl[4];
            LDSM4(bh, rb);
            LDSM4(bl, rb + MATB);
#pragma unroll
            for (int i = 0; i < 2; i++) {
                MMA16816(acc[i][jp * 2 + 0], ah[i], bh[0], bh[1]);
                MMA16816(acc[i][jp * 2 + 0], ah[i], bl[0], bl[1]);
                MMA16816(acc[i][jp * 2 + 0], al[i], bh[0], bh[1]);
                MMA16816(acc[i][jp * 2 + 1], ah[i], bh[2], bh[3]);
                MMA16816(acc[i][jp * 2 + 1], ah[i], bl[2], bl[3]);
                MMA16816(acc[i][jp * 2 + 1], al[i], bh[2], bh[3]);
            }
        }

        if (c + 1 < NC) {
            const uint32_t nb = (buf ^ 1) * BUFB;
            uint4 hi, lo;
            cvt8(pfa0, pfa1, hi, lo);
            *(uint4*)(smem + nb + soff) = hi;
            *(uint4*)(smem + nb + MATB + soff) = lo;
            *(uint4*)(smem + nb + 2 * MATB + soff) = pbh;
            *(uint4*)(smem + nb + 3 * MATB + soff) = pbl;
        }
        __syncthreads();
    }

    const int rbase = warp_m + (lane >> 2);
    const int cbase = warp_n + (lane & 3) * 2;
#pragma unroll
    for (int i = 0; i < 2; i++) {
#pragma unroll
        for (int h = 0; h < 2; h++) {
            const size_t row = bm + rbase + i * 16 + h * 8;
#pragma unroll
            for (int j = 0; j < 8; j++) {
                const int cg = cbase + j * 8;
                uint32_t hi, lo;
                split_pair(acc[i][j][h * 2 + 0], acc[i][j][h * 2 + 1], hi, lo);
                *(uint32_t*)(oh + row * (size_t)ldc + bn + cg) = hi;
                *(uint32_t*)(ol + row * (size_t)ldc + bn + cg) = lo;
            }
        }
    }
}

// ======================= fused logits+zsq, BK=32, Sraw -> fp16 ================
// grid (12, BATCH/128): x<8: Sh = fp16(xh.Qh^T) ; x>=8: zsq += |xh.Wh^T + b|^2
__global__ __launch_bounds__(256, 2) void fused_logits_zsq_bk32(
    const __half* __restrict__ xh,
    const __half* __restrict__ Qh,
    const __half* __restrict__ Wh, const float* __restrict__ bias,
    __half* __restrict__ Sh, float* __restrict__ zsq) {
    extern __shared__ __align__(128) char smem[];
    const uint32_t sb = smem_u32(smem);
    const int tid = threadIdx.x;
    const int wid = tid >> 5, lane = tid & 31;
    const bool is_w = blockIdx.x >= 8;
    const size_t bm = (size_t)blockIdx.y * 128;
    const size_t bn = is_w ? (size_t)(blockIdx.x - 8) * 128 : (size_t)blockIdx.x * 128;
    const int warp_m = (wid >> 1) * 32;
    const int warp_n = (wid & 1) * 64;
    const int K = DIM, NC = DIM >> 5;   // 16 chunks of 32

    float acc[2][8][4];
#pragma unroll
    for (int i = 0; i < 2; i++)
#pragma unroll
        for (int j = 0; j < 8; j++)
#pragma unroll
            for (int k = 0; k < 4; k++) acc[i][j][k] = 0.0f;

    const __half* Ahg = xh + bm * K;
    const __half* Bhg = (is_w ? Wh : Qh) + bn * K;

    const int f_r0 = tid >> 2, f_r1 = (tid + 256) >> 2;
    const int f_s = (tid & 3) << 3;
    const uint32_t so0 = (uint32_t)(f_r0 * 80 + (tid & 3) * 16);
    const uint32_t so1 = (uint32_t)(f_r1 * 80 + (tid & 3) * 16);

    {
        *(uint4*)(smem + so0) = *(const uint4*)(Ahg + (size_t)f_r0 * K + f_s);
        *(uint4*)(smem + so1) = *(const uint4*)(Ahg + (size_t)f_r1 * K + f_s);
        *(uint4*)(smem + MAT32 + so0) = *(const uint4*)(Bhg + (size_t)f_r0 * K + f_s);
        *(uint4*)(smem + MAT32 + so1) = *(const uint4*)(Bhg + (size_t)f_r1 * K + f_s);
    }
    __syncthreads();

    const int a_row = lane & 15;
    const int a_kb = ((lane >> 4) << 3) * 2;
    const int b_n = ((lane >> 4) << 3) + (lane & 7);
    const int b_kb = (lane & 8) * 2;

    uint4 pa0, pa1, pb0, pb1;
    for (int c = 0; c < NC; ++c) {
        const int buf = c & 1;
        const uint32_t base = sb + buf * BUF32;

        if (c + 1 < NC) {
            const int k0 = (c + 1) << 5;
            pa0 = *(const uint4*)(Ahg + (size_t)f_r0 * K + k0 + f_s);
            pa1 = *(const uint4*)(Ahg + (size_t)f_r1 * K + k0 + f_s);
            pb0 = *(const uint4*)(Bhg + (size_t)f_r0 * K + k0 + f_s);
            pb1 = *(const uint4*)(Bhg + (size_t)f_r1 * K + k0 + f_s);
        }

#pragma unroll
        for (int kk = 0; kk < 2; kk++) {
            const int kb = kk * 32;
            uint32_t ah[2][4];
#pragma unroll
            for (int i = 0; i < 2; i++) {
                uint32_t ra = base + (uint32_t)((warp_m + i * 16 + a_row) * 80) + kb + a_kb;
                LDSM4(ah[i], ra);
            }
#pragma unroll
            for (int jp = 0; jp < 4; jp++) {
                uint32_t rb = base + MAT32 +
                              (uint32_t)((warp_n + jp * 16 + b_n) * 80) + kb + b_kb;
                uint32_t bh[4];
                LDSM4(bh, rb);
#pragma unroll
                for (int i = 0; i < 2; i++) {
                    MMA16816(acc[i][jp * 2 + 0], ah[i], bh[0], bh[1]);
                    MMA16816(acc[i][jp * 2 + 1], ah[i], bh[2], bh[3]);
                }
            }
        }

        if (c + 1 < NC) {
            const uint32_t nb = (buf ^ 1) * BUF32;
            *(uint4*)(smem + nb + so0) = pa0;
            *(uint4*)(smem + nb + so1) = pa1;
            *(uint4*)(smem + nb + MAT32 + so0) = pb0;
            *(uint4*)(smem + nb + MAT32 + so1) = pb1;
        }
        __syncthreads();
    }

    const int rbase = warp_m + (lane >> 2);
    const int cbase = warp_n + (lane & 3) * 2;
#pragma unroll
    for (int i = 0; i < 2; i++) {
#pragma unroll
        for (int h = 0; h < 2; h++) {
            const size_t row = bm + rbase + i * 16 + h * 8;
            if (is_w) {
                float s = 0.0f;
#pragma unroll
                for (int j = 0; j < 8; j++) {
                    const int cg = cbase + j * 8;
                    float v0 = acc[i][j][h * 2 + 0] + bias[bn + cg];
                    float v1 = acc[i][j][h * 2 + 1] + bias[bn + cg + 1];
                    s += v0 * v0 + v1 * v1;
                }
                s += __shfl_xor_sync(0xffffffffu, s, 1);
                s += __shfl_xor_sync(0xffffffffu, s, 2);
                if ((lane & 3) == 0) atomicAdd(zsq + row, s);
            } else {
                __half* srow = Sh + row * (size_t)NPROTO + bn;
#pragma unroll
                for (int j = 0; j < 8; j++) {
                    const int cg = cbase + j * 8;
                    __half2 hv = __floats2half2_rn(acc[i][j][h * 2 + 0],
                                                   acc[i][j][h * 2 + 1]);
                    *(uint32_t*)(srow + cg) = *(uint32_t*)&hv;
                }
            }
        }
    }
}

// blended = A(fp16) @ B(fp16)^T, 1-pass, BK=32, fp32 out
__global__ __launch_bounds__(256, 2) void hmma_gemm1p_bk32(
    const __half* __restrict__ Ah, const __half* __restrict__ Bh,
    float* __restrict__ C, int K, int ldc) {
    extern __shared__ __align__(128) char smem[];
    const uint32_t sb = smem_u32(smem);
    const int tid = threadIdx.x;
    const int wid = tid >> 5, lane = tid & 31;
    const size_t bm = (size_t)blockIdx.y * 128;
    const size_t bn = (size_t)blockIdx.x * 128;
    const int warp_m = (wid >> 1) * 32;
    const int warp_n = (wid & 1) * 64;
    const int NC = K >> 5;

    float acc[2][8][4];
#pragma unroll
    for (int i = 0; i < 2; i++)
#pragma unroll
        for (int j = 0; j < 8; j++)
#pragma unroll
            for (int k = 0; k < 4; k++) acc[i][j][k] = 0.0f;

    const __half* Ahg = Ah + bm * K;
    const __half* Bhg = Bh + bn * K;

    const int f_r0 = tid >> 2, f_r1 = (tid + 256) >> 2;
    const int f_s = (tid & 3) << 3;
    const uint32_t so0 = (uint32_t)(f_r0 * 80 + (tid & 3) * 16);
    const uint32_t so1 = (uint32_t)(f_r1 * 80 + (tid & 3) * 16);

    {
        *(uint4*)(smem + so0) = *(const uint4*)(Ahg + (size_t)f_r0 * K + f_s);
        *(uint4*)(smem + so1) = *(const uint4*)(Ahg + (size_t)f_r1 * K + f_s);
        *(uint4*)(smem + MAT32 + so0) = *(const uint4*)(Bhg + (size_t)f_r0 * K + f_s);
        *(uint4*)(smem + MAT32 + so1) = *(const uint4*)(Bhg + (size_t)f_r1 * K + f_s);
    }
    __syncthreads();

    const int a_row = lane & 15;
    const int a_kb = ((lane >> 4) << 3) * 2;
    const int b_n = ((lane >> 4) << 3) + (lane & 7);
    const int b_kb = (lane & 8) * 2;

    uint4 pa0, pa1, pb0, pb1;
    for (int c = 0; c < NC; ++c) {
        const int buf = c & 1;
        const uint32_t base = sb + buf * BUF32;

        if (c + 1 < NC) {
            const int k0 = (c + 1) << 5;
            pa0 = *(const uint4*)(Ahg + (size_t)f_r0 * K + k0 + f_s);
            pa1 = *(const uint4*)(Ahg + (size_t)f_r1 * K + k0 + f_s);
            pb0 = *(const uint4*)(Bhg + (size_t)f_r0 * K + k0 + f_s);
            pb1 = *(const uint4*)(Bhg + (size_t)f_r1 * K + k0 + f_s);
        }

#pragma unroll
        for (int kk = 0; kk < 2; kk++) {
            const int kb = kk * 32;
            uint32_t ah[2][4];
#pragma unroll
            for (int i = 0; i < 2; i++) {
                uint32_t ra = base + (uint32_t)((warp_m + i * 16 + a_row) * 80) + kb + a_kb;
                LDSM4(ah[i], ra);
            }
#pragma unroll
            for (int jp = 0; jp < 4; jp++) {
                uint32_t rb = base + MAT32 +
                              (uint32_t)((warp_n + jp * 16 + b_n) * 80) + kb + b_kb;
                uint32_t bh[4];
                LDSM4(bh, rb);
#pragma unroll
                for (int i = 0; i < 2; i++) {
                    MMA16816(acc[i][jp * 2 + 0], ah[i], bh[0], bh[1]);
                    MMA16816(acc[i][jp * 2 + 1], ah[i], bh[2], bh[3]);
                }
            }
        }

        if (c + 1 < NC) {
            const uint32_t nb = (buf ^ 1) * BUF32;
            *(uint4*)(smem + nb + so0) = pa0;
            *(uint4*)(smem + nb + so1) = pa1;
            *(uint4*)(smem + nb + MAT32 + so0) = pb0;
            *(uint4*)(smem + nb + MAT32 + so1) = pb1;
        }
        __syncthreads();
    }

    const int rbase = warp_m + (lane >> 2);
    const int cbase = warp_n + (lane & 3) * 2;
#pragma unroll
    for (int i = 0; i < 2; i++) {
#pragma unroll
        for (int h = 0; h < 2; h++) {
            const size_t row = bm + rbase + i * 16 + h * 8;
            float* crow = C + row * (size_t)ldc + bn;
#pragma unroll
            for (int j = 0; j < 8; j++) {
                const int cg = cbase + j * 8;
                *(float2*)(crow + cg) =
                    make_float2(acc[i][j][h * 2 + 0], acc[i][j][h * 2 + 1]);
            }
        }
    }
}

// ======================= small kernels =======================
__device__ __forceinline__ float wsum(float v) {
#pragma unroll
    for (int o = 16; o; o >>= 1) v += __shfl_xor_sync(0xffffffffu, v, o);
    return v;
}
__device__ __forceinline__ float wmax(float v) {
#pragma unroll
    for (int o = 16; o; o >>= 1) v = fmaxf(v, __shfl_xor_sync(0xffffffffu, v, o));
    return v;
}

// psq2[row] = sum(P[row]^2) - 2 * dot(P[row], b)
__global__ __launch_bounds__(128) void row_psq2(const float* __restrict__ P,
                                                const float* __restrict__ b,
                                                float* __restrict__ out) {
    size_t row = blockIdx.x;
    const float4* p = (const float4*)(P + row * 512);
    float4 v = p[threadIdx.x];
    float4 bb = ((const float4*)b)[threadIdx.x];
    float s = v.x * v.x + v.y * v.y + v.z * v.z + v.w * v.w
            - 2.0f * (v.x * bb.x + v.y * bb.y + v.z * bb.z + v.w * bb.w);
    s = wsum(s);
    __shared__ float red[4];
    if ((threadIdx.x & 31) == 0) red[threadIdx.x >> 5] = s;
    __syncthreads();
    if (threadIdx.x == 0) out[row] = red[0] + red[1] + red[2] + red[3];
}

// dist + softmax over rows of 1024; reads fp16 Sraw (in Sh), writes fp32 weights
// + normalized fp16 back to Sh (in-place, same thread same address)
__global__ __launch_bounds__(256) void softmax_dist_1024(
    float* __restrict__ Wt, const float* __restrict__ zsq,
    const float* __restrict__ psq2, const float* __restrict__ temp_raw,
    __half* __restrict__ Sh) {
    size_t row = blockIdx.x;
    uint2 sraw = *(uint2*)(Sh + row * 1024 + threadIdx.x * 4);
    __half2 sh0 = *(__half2*)&sraw.x;
    __half2 sh1 = *(__half2*)&sraw.y;
    float2 f0 = __half22float2(sh0);
    float2 f1 = __half22float2(sh1);
    float4 pq = ((const float4*)psq2)[threadIdx.x];
    float zr = zsq[row];
    float t = temp_raw[0];
    float temp = 1.0f / (1.0f + expf(-t)) * 0.999f + 0.001f;
    float invt = 1.0f / temp;

    float4 v;
    v.x = -sqrtf(fmaxf(zr + pq.x - 2.0f * f0.x, 1e-12f)) * invt;
    v.y = -sqrtf(fmaxf(zr + pq.y - 2.0f * f0.y, 1e-12f)) * invt;
    v.z = -sqrtf(fmaxf(zr + pq.z - 2.0f * f1.x, 1e-12f)) * invt;
    v.w = -sqrtf(fmaxf(zr + pq.w - 2.0f * f1.y, 1e-12f)) * invt;

    __shared__ float red[8];
    float m = fmaxf(fmaxf(v.x, v.y), fmaxf(v.z, v.w));
    m = wmax(m);
    if ((threadIdx.x & 31) == 0) red[threadIdx.x >> 5] = m;
    __syncthreads();
    if (threadIdx.x < 32) {
        float q = (threadIdx.x < 8) ? red[threadIdx.x] : -INFINITY;
        q = wmax(q);
        if (threadIdx.x == 0) red[0] = q;
    }
    __syncthreads();
    m = red[0];
    __syncthreads();

    v.x = fexp(v.x - m); v.y = fexp(v.y - m);
    v.z = fexp(v.z - m); v.w = fexp(v.w - m);
    float s = v.x + v.y + v.z + v.w;
    s = wsum(s);
    __shared__ float red2[8];
    if ((threadIdx.x & 31) == 0) red2[threadIdx.x >> 5] = s;
    __syncthreads();
    if (threadIdx.x < 32) {
        float q = (threadIdx.x < 8) ? red2[threadIdx.x] : 0.0f;
        q = wsum(q);
        if (threadIdx.x == 0) red2[0] = q;
    }
    __syncthreads();
    float inv = 1.0f / red2[0];
    v.x *= inv; v.y *= inv; v.z *= inv; v.w *= inv;
    ((float4*)(Wt + row * 1024))[threadIdx.x] = v;

    __half2 h0 = __floats2half2_rn(v.x, v.y);
    __half2 h1 = __floats2half2_rn(v.z, v.w);
    *(uint2*)(Sh + row * 1024 + threadIdx.x * 4) =
        make_uint2(*(uint32_t*)&h0, *(uint32_t*)&h1);
}

// convert fp32 array to fp16 (hi only)
__global__ __launch_bounds__(256) void split_hi(const float4* __restrict__ src,
                                                uint2* __restrict__ hi, int n4) {
    int i = blockIdx.x * 256 + threadIdx.x;
    if (i >= n4) return;
    float4 v = src[i];
    __half2 h0 = __floats2half2_rn(v.x, v.y);
    __half2 h1 = __floats2half2_rn(v.z, v.w);
    hi[i] = make_uint2(*(uint32_t*)&h0, *(uint32_t*)&h1);
}

// transpose + split: src [rows, cols] fp32 -> dst [cols, rows] fp16 hi (+ optional lo)
__global__ __launch_bounds__(256) void transpose_split(const float* __restrict__ src,
                                                       __half* __restrict__ dh,
                                                       __half* __restrict__ dl,
                                                       int rows, int cols) {
    __shared__ float t[32][33];
    int bx = blockIdx.x * 32;
    int by = blockIdx.y * 32;
    int tx = threadIdx.x & 31, ty = (threadIdx.x >> 5) * 4;
#pragma unroll
    for (int i = 0; i < 4; i++)
        t[ty + i][tx] = src[(size_t)(by + ty + i) * cols + bx + tx];
    __syncthreads();
#pragma unroll
    for (int i = 0; i < 4; i++) {
        float v = t[tx][ty + i];
        __half hv = __float2half_rn(v);
        size_t off = (size_t)(bx + ty + i) * rows + by + tx;
        dh[off] = hv;
        if (dl) dl[off] = __float2half_rn(v - __half2float(hv));
    }
}

extern "C" void kernel_launch(void* const* d_in, const int* in_sizes, int n_in,
                              void* d_out, int out_size) {
    const float* x  = (const float*)d_in[0];
    const float* W  = (const float*)d_in[1];
    const float* b  = (const float*)d_in[2];
    const float* P  = (const float*)d_in[3];
    const float* tr = (const float*)d_in[4];

    float* blended = (float*)d_out;
    float* weights = (float*)d_out + (size_t)BATCH * DIM;

    __half *xh, *Wh, *WTh, *WTl, *PTh, *Qh, *Ql, *sw;
    float *zsq, *psq2;
    cudaGetSymbolAddress((void**)&xh, g_xh);
    cudaGetSymbolAddress((void**)&Wh, g_Wh);
    cudaGetSymbolAddress((void**)&WTh, g_WTh); cudaGetSymbolAddress((void**)&WTl, g_WTl);
    cudaGetSymbolAddress((void**)&PTh, g_PTh);
    cudaGetSymbolAddress((void**)&Qh, g_Qh);   cudaGetSymbolAddress((void**)&Ql, g_Ql);
    cudaGetSymbolAddress((void**)&sw, g_sw);
    cudaGetSymbolAddress((void**)&zsq, g_zsq); cudaGetSymbolAddress((void**)&psq2, g_psq2);

    cudaFuncSetAttribute((const void*)hmma_gemm3p, cudaFuncAttributeMaxDynamicSharedMemorySize, SMEM_TOTAL);
    cudaFuncSetAttribute((const void*)fused_logits_zsq_bk32, cudaFuncAttributeMaxDynamicSharedMemorySize, SMEM32);
    cudaFuncSetAttribute((const void*)hmma_gemm1p_bk32, cudaFuncAttributeMaxDynamicSharedMemorySize, SMEM32);

    cudaMemsetAsync(zsq, 0, BATCH * sizeof(float));

    // psq2 = |p|^2 - 2 p.b
    row_psq2<<<NPROTO, 128>>>(P, b, psq2);

    // operand prep
    split_hi<<<(BATCH * DIM / 4 + 255) / 256, 256>>>((const float4*)x, (uint2*)xh, BATCH * DIM / 4);
    split_hi<<<(DIM * DIM / 4 + 255) / 256, 256>>>((const float4*)W, (uint2*)Wh, DIM * DIM / 4);
    transpose_split<<<dim3(16, 16), 256>>>(W, WTh, WTl, DIM, DIM);
    transpose_split<<<dim3(16, 32), 256>>>(P, PTh, nullptr, NPROTO, DIM);

    // Q = P @ W (3-pass, fp32-accurate), write fp16 hi/lo
    hmma_gemm3p<<<dim3(DIM / 128, NPROTO / 128), 256, SMEM_TOTAL>>>(
        P, WTh, WTl, Qh, Ql, DIM, DIM);

    // fused: Sraw(fp16) = xh.Qh^T + zsq (both 1-pass, BK=32)
    fused_logits_zsq_bk32<<<dim3(12, BATCH / 128), 256, SMEM32>>>(
        xh, Qh, Wh, b, sw, zsq);

    // dist + softmax; reads fp16 Sraw, writes fp32 weights + fp16 weights (in-place)
    softmax_dist_1024<<<BATCH, 256>>>(weights, zsq, psq2, tr, sw);

    // blended = weights @ P (1-pass, BK=32)
    hmma_gemm1p_bk32<<<dim3(DIM / 128, BATCH / 128), 256, SMEM32>>>(
        sw, PTh, blended, NPROTO, DIM);
}